// round 9
// baseline (speedup 1.0000x reference)
#include <cuda_runtime.h>

// ---------------- problem constants ----------------
#define Bb 4
#define NN 1024
#define DIMV 1024
#define HH 16
#define DHd 64
#define VOC 129            // 2*MAXREL+1
#define MAXREL 64
#define TOPKv 256
#define BHH (Bb*HH)        // 64
#define ROWS (BHH*NN)      // 65536
#define SCALEv 0.125f      // DH^-0.5

typedef unsigned long long u64;

// ---------------- device scratch (no allocs allowed) ----------------
__device__ float g_Q[ROWS*DHd];
__device__ float g_K[ROWS*DHd];
__device__ float g_V[ROWS*DHd];
__device__ float g_S[(size_t)ROWS*NN];        // 256 MB scores
__device__ float g_QR[ROWS*VOC];              // q @ rel_k_emb^T
__device__ float g_CW[ROWS*TOPKv];            // compact attn weights
__device__ int   g_CI[ROWS*TOPKv];            // compact attn column indices
__device__ float g_ARel[ROWS*DHd];            // attn @ rel_v
__device__ float g_VA[ROWS*DHd];
__device__ float g_VB[ROWS*DHd];
__device__ float g_Res[ROWS*DHd];

// ---------------- packed f32x2 helpers ----------------
__device__ __forceinline__ void ffma2(u64 &d, u64 a, u64 b) {
    asm("fma.rn.f32x2 %0, %1, %2, %0;" : "+l"(d) : "l"(a), "l"(b));
}
__device__ __forceinline__ u64 dup2(float x) {
    u64 r; asm("mov.b64 %0, {%1, %1};" : "=l"(r) : "f"(x)); return r;
}
__device__ __forceinline__ float2 unpack2(u64 v) {
    float2 f; asm("mov.b64 {%0, %1}, %2;" : "=f"(f.x), "=f"(f.y) : "l"(v)); return f;
}

// =====================================================================
// Kernel 1: qkv = x @ Wqkv^T + bqkv, scattered into per-head Q/K/V.
// 128x128 tile, BK=16, 256 threads, reg double-buffered loads, FFMA2.
// =====================================================================
__global__ __launch_bounds__(256) void k_gemm_qkv(const float* __restrict__ X,
                                                  const float* __restrict__ W,
                                                  const float* __restrict__ bias) {
    __shared__ float As[16][128];
    __shared__ float Bs[16][128];
    int tid = threadIdx.x;
    int tx = tid & 15, ty = tid >> 4;
    int m0 = blockIdx.y * 128, c0 = blockIdx.x * 128;
    u64 acc2[8][4] = {};

    int lr0 = tid >> 2, lk = (tid & 3) * 4;
    int lr1 = lr0 + 64;
    const float* pa0 = &X[(size_t)(m0 + lr0) * DIMV + lk];
    const float* pa1 = &X[(size_t)(m0 + lr1) * DIMV + lk];
    const float* pb0 = &W[(size_t)(c0 + lr0) * DIMV + lk];
    const float* pb1 = &W[(size_t)(c0 + lr1) * DIMV + lk];

    float4 ra0 = *(const float4*)pa0;
    float4 ra1 = *(const float4*)pa1;
    float4 rb0 = *(const float4*)pb0;
    float4 rb1 = *(const float4*)pb1;

    for (int k0 = 0; k0 < DIMV; k0 += 16) {
        As[lk+0][lr0] = ra0.x; As[lk+1][lr0] = ra0.y; As[lk+2][lr0] = ra0.z; As[lk+3][lr0] = ra0.w;
        As[lk+0][lr1] = ra1.x; As[lk+1][lr1] = ra1.y; As[lk+2][lr1] = ra1.z; As[lk+3][lr1] = ra1.w;
        Bs[lk+0][lr0] = rb0.x; Bs[lk+1][lr0] = rb0.y; Bs[lk+2][lr0] = rb0.z; Bs[lk+3][lr0] = rb0.w;
        Bs[lk+0][lr1] = rb1.x; Bs[lk+1][lr1] = rb1.y; Bs[lk+2][lr1] = rb1.z; Bs[lk+3][lr1] = rb1.w;
        __syncthreads();
        if (k0 + 16 < DIMV) {
            ra0 = *(const float4*)(pa0 + k0 + 16);
            ra1 = *(const float4*)(pa1 + k0 + 16);
            rb0 = *(const float4*)(pb0 + k0 + 16);
            rb1 = *(const float4*)(pb1 + k0 + 16);
        }
        #pragma unroll
        for (int k = 0; k < 16; k++) {
            float4 a0 = *(const float4*)&As[k][ty * 4];
            float4 a1 = *(const float4*)&As[k][ty * 4 + 64];
            ulonglong2 b0 = *(const ulonglong2*)&Bs[k][tx * 4];
            ulonglong2 b1 = *(const ulonglong2*)&Bs[k][tx * 4 + 64];
            u64 ad[8];
            ad[0]=dup2(a0.x); ad[1]=dup2(a0.y); ad[2]=dup2(a0.z); ad[3]=dup2(a0.w);
            ad[4]=dup2(a1.x); ad[5]=dup2(a1.y); ad[6]=dup2(a1.z); ad[7]=dup2(a1.w);
            #pragma unroll
            for (int i = 0; i < 8; i++) {
                ffma2(acc2[i][0], ad[i], b0.x);
                ffma2(acc2[i][1], ad[i], b0.y);
                ffma2(acc2[i][2], ad[i], b1.x);
                ffma2(acc2[i][3], ad[i], b1.y);
            }
        }
        __syncthreads();
    }
    #pragma unroll
    for (int ih = 0; ih < 2; ih++) {
        #pragma unroll
        for (int i = 0; i < 4; i++) {
            int m = m0 + ih * 64 + ty * 4 + i;
            int b = m >> 10, n = m & 1023;
            #pragma unroll
            for (int jh = 0; jh < 2; jh++) {
                int c = c0 + jh * 64 + tx * 4;
                float2 lo = unpack2(acc2[ih*4+i][jh*2+0]);
                float2 hi = unpack2(acc2[ih*4+i][jh*2+1]);
                float4 v;
                v.x = lo.x + bias[c+0];
                v.y = lo.y + bias[c+1];
                v.z = hi.x + bias[c+2];
                v.w = hi.y + bias[c+3];
                int part = c >> 10;
                int hc = c & 1023;
                int h = hc >> 6, dh = hc & 63;
                float* dst = (part == 0) ? g_Q : ((part == 1) ? g_K : g_V);
                *(float4*)&dst[((size_t)((b * HH + h) * NN + n)) * DHd + dh] = v;
            }
        }
    }
}

// =====================================================================
// Kernel 2: QR[row][t] = Q[row] . rel_k_emb[t]
// =====================================================================
__global__ void k_qr(const float* __restrict__ relk) {
    __shared__ float sQ[32][65];
    int tid = threadIdx.x;
    int row0 = blockIdx.x * 32;
    for (int e = tid; e < 32 * 64; e += 256) {
        int r = e >> 6, d = e & 63;
        sQ[r][d] = g_Q[(size_t)(row0 + r) * DHd + d];
    }
    __syncthreads();
    for (int task = tid; task < 32 * VOC; task += 256) {
        int r = task / VOC, t = task % VOC;
        const float* rk = &relk[t * DHd];
        float acc = 0.f;
        #pragma unroll
        for (int d = 0; d < 64; d++) acc += sQ[r][d] * __ldg(&rk[d]);
        g_QR[(size_t)(row0 + r) * VOC + t] = acc;
    }
}

// =====================================================================
// Kernel 3: S = SCALE*Q.K^T + QR gather.  128x128 tile, BK=16, FFMA2,
// register double-buffered gmem loads.  grid (8, 8, 64)
// =====================================================================
__global__ __launch_bounds__(256) void k_scores() {
    __shared__ float Qs[16][128];
    __shared__ float Ks[16][128];
    int tid = threadIdx.x;
    int tx = tid & 15, ty = tid >> 4;
    int bh = blockIdx.z;
    int i0 = blockIdx.y * 128, j0 = blockIdx.x * 128;
    u64 acc2[8][4] = {};

    int lr0 = tid >> 2, lk = (tid & 3) * 4;
    int lr1 = lr0 + 64;
    const float* pq0 = &g_Q[(size_t)(bh * NN + i0 + lr0) * DHd + lk];
    const float* pq1 = &g_Q[(size_t)(bh * NN + i0 + lr1) * DHd + lk];
    const float* pk0 = &g_K[(size_t)(bh * NN + j0 + lr0) * DHd + lk];
    const float* pk1 = &g_K[(size_t)(bh * NN + j0 + lr1) * DHd + lk];

    float4 rq0 = *(const float4*)pq0;
    float4 rq1 = *(const float4*)pq1;
    float4 rk0 = *(const float4*)pk0;
    float4 rk1 = *(const float4*)pk1;

    for (int k0 = 0; k0 < DHd; k0 += 16) {
        Qs[lk+0][lr0] = rq0.x; Qs[lk+1][lr0] = rq0.y; Qs[lk+2][lr0] = rq0.z; Qs[lk+3][lr0] = rq0.w;
        Qs[lk+0][lr1] = rq1.x; Qs[lk+1][lr1] = rq1.y; Qs[lk+2][lr1] = rq1.z; Qs[lk+3][lr1] = rq1.w;
        Ks[lk+0][lr0] = rk0.x; Ks[lk+1][lr0] = rk0.y; Ks[lk+2][lr0] = rk0.z; Ks[lk+3][lr0] = rk0.w;
        Ks[lk+0][lr1] = rk1.x; Ks[lk+1][lr1] = rk1.y; Ks[lk+2][lr1] = rk1.z; Ks[lk+3][lr1] = rk1.w;
        __syncthreads();
        if (k0 + 16 < DHd) {
            rq0 = *(const float4*)(pq0 + k0 + 16);
            rq1 = *(const float4*)(pq1 + k0 + 16);
            rk0 = *(const float4*)(pk0 + k0 + 16);
            rk1 = *(const float4*)(pk1 + k0 + 16);
        }
        #pragma unroll
        for (int k = 0; k < 16; k++) {
            float4 a0 = *(const float4*)&Qs[k][ty * 4];
            float4 a1 = *(const float4*)&Qs[k][ty * 4 + 64];
            ulonglong2 b0 = *(const ulonglong2*)&Ks[k][tx * 4];
            ulonglong2 b1 = *(const ulonglong2*)&Ks[k][tx * 4 + 64];
            u64 ad[8];
            ad[0]=dup2(a0.x); ad[1]=dup2(a0.y); ad[2]=dup2(a0.z); ad[3]=dup2(a0.w);
            ad[4]=dup2(a1.x); ad[5]=dup2(a1.y); ad[6]=dup2(a1.z); ad[7]=dup2(a1.w);
            #pragma unroll
            for (int i = 0; i < 8; i++) {
                ffma2(acc2[i][0], ad[i], b0.x);
                ffma2(acc2[i][1], ad[i], b0.y);
                ffma2(acc2[i][2], ad[i], b1.x);
                ffma2(acc2[i][3], ad[i], b1.y);
            }
        }
        __syncthreads();
    }
    #pragma unroll
    for (int ih = 0; ih < 2; ih++) {
        #pragma unroll
        for (int i = 0; i < 4; i++) {
            int ii = i0 + ih * 64 + ty * 4 + i;
            const float* qr = &g_QR[(size_t)(bh * NN + ii) * VOC];
            size_t sbase = ((size_t)(bh * NN + ii)) * NN;
            #pragma unroll
            for (int jh = 0; jh < 2; jh++) {
                int jj0 = j0 + jh * 64 + tx * 4;
                float2 lo = unpack2(acc2[ih*4+i][jh*2+0]);
                float2 hi = unpack2(acc2[ih*4+i][jh*2+1]);
                float accv[4] = {lo.x, lo.y, hi.x, hi.y};
                float4 v;
                #pragma unroll
                for (int j = 0; j < 4; j++) {
                    int jj = jj0 + j;
                    int d = ii - jj;
                    d = d < -MAXREL ? -MAXREL : (d > MAXREL ? MAXREL : d);
                    ((float*)&v)[j] = accv[j] * SCALEv + qr[d + MAXREL];
                }
                *(float4*)&g_S[sbase + jj0] = v;
            }
        }
    }
}

// float -> order-preserving uint key
__device__ __forceinline__ unsigned ftokey(float f) {
    unsigned u = __float_as_uint(f);
    return (u & 0x80000000u) ? ~u : (u | 0x80000000u);
}

// =====================================================================
// Kernel 4 (fused): radix-select exact top-256 threshold + masked softmax
// + deterministic compaction + rel_v bucket trick -> ARel.
// Plain atomic histogram (fastest proven); parallel ARel dot.
// One block (256 threads) per score row.
// =====================================================================
__global__ __launch_bounds__(256) void k_select(const float* __restrict__ relv) {
    __shared__ float sbuf[1024];
    __shared__ int   hist[256];
    __shared__ float wredf[8];
    __shared__ float wredf2[8];
    __shared__ int   wredi[8];
    __shared__ float rbin[VOC];
    __shared__ float sred[4][64];
    __shared__ unsigned sh_selb;
    __shared__ int      sh_rem;

    int row = blockIdx.x;
    int tid = threadIdx.x;
    int lane = tid & 31, wid = tid >> 5;
    int i = row & (NN - 1);
    const float* src = &g_S[(size_t)row * NN];

    float4 lv4 = *(const float4*)&src[tid * 4];
    float lv[4] = {lv4.x, lv4.y, lv4.z, lv4.w};
    unsigned kv[4];
    #pragma unroll
    for (int r = 0; r < 4; r++) kv[r] = ftokey(lv[r]);

    // ---- row max ----
    float m = fmaxf(fmaxf(lv[0], lv[1]), fmaxf(lv[2], lv[3]));
    #pragma unroll
    for (int off = 16; off > 0; off >>= 1)
        m = fmaxf(m, __shfl_xor_sync(0xffffffffu, m, off));
    if (lane == 0) wredf[wid] = m;
    __syncthreads();
    float rmax = wredf[0];
    #pragma unroll
    for (int w = 1; w < 8; w++) rmax = fmaxf(rmax, wredf[w]);

    // ---- radix select: exact key of the 256th largest ----
    unsigned prefix = 0;
    int need = TOPKv;
    for (int round = 3; round >= 0; round--) {
        hist[tid] = 0;
        __syncthreads();
        unsigned mask = (round == 3) ? 0u : (0xFFFFFFFFu << ((round + 1) * 8));
        #pragma unroll
        for (int r = 0; r < 4; r++) {
            if ((kv[r] & mask) == prefix)
                atomicAdd(&hist[(kv[r] >> (round * 8)) & 255], 1);
        }
        __syncthreads();
        int h = hist[tid];
        int s = h;          // inclusive suffix within warp
        #pragma unroll
        for (int off = 1; off < 32; off <<= 1) {
            int v = __shfl_down_sync(0xffffffffu, s, off);
            if (lane + off < 32) s += v;
        }
        int wtot = __shfl_sync(0xffffffffu, s, 0);
        if (lane == 0) wredi[wid] = wtot;
        __syncthreads();
        int tail = 0;
        #pragma unroll
        for (int w = 0; w < 8; w++) if (w > wid) tail += wredi[w];
        int Sb = s + tail;          // count of keys >= bin tid
        int Sb1 = Sb - h;           // count of keys >= bin tid+1
        if (Sb >= need && Sb1 < need) { sh_selb = (unsigned)tid; sh_rem = Sb1; }
        __syncthreads();
        prefix |= sh_selb << (round * 8);
        need -= sh_rem;
        __syncthreads();
    }
    unsigned thrkey = prefix;

    // ---- masked exp + block sum ----
    float lsum = 0.f;
    #pragma unroll
    for (int r = 0; r < 4; r++) {
        int j = tid * 4 + r;
        float e;
        if (kv[r] >= thrkey) { e = __expf(lv[r] - rmax); lsum += e; }
        else e = -1.0f;
        sbuf[j] = e;
    }
    float ws = lsum;
    #pragma unroll
    for (int off = 16; off > 0; off >>= 1)
        ws += __shfl_xor_sync(0xffffffffu, ws, off);
    if (lane == 0) wredf[wid] = ws;
    __syncthreads();
    float tot = 0.f;
    #pragma unroll
    for (int w = 0; w < 8; w++) tot += wredf[w];
    float inv = 1.0f / tot;

    // ---- rel_v buckets ----
    if (tid >= 1 && tid < 128) {
        int j = i + MAXREL - tid;
        float v = 0.f;
        if (j >= 0 && j < NN) {
            float e = sbuf[j];
            if (e >= 0.f) v = e * inv;
        }
        rbin[tid] = v;
    }
    float s0 = 0.f, s128 = 0.f;
    #pragma unroll
    for (int r = 0; r < 4; r++) {
        int j = tid * 4 + r;
        float e = sbuf[j];
        float a = (e >= 0.f) ? e * inv : 0.f;
        if (j >= i + MAXREL) s0 += a;
        if (j <= i - MAXREL) s128 += a;
    }
    #pragma unroll
    for (int off = 16; off > 0; off >>= 1) {
        s0   += __shfl_xor_sync(0xffffffffu, s0, off);
        s128 += __shfl_xor_sync(0xffffffffu, s128, off);
    }
    __syncthreads();
    if (lane == 0) { wredf[wid] = s0; wredf2[wid] = s128; }
    __syncthreads();
    if (tid == 0) {
        float a = 0.f, b = 0.f;
        #pragma unroll
        for (int w = 0; w < 8; w++) { a += wredf[w]; b += wredf2[w]; }
        rbin[0] = a; rbin[MAXREL * 2] = b;
    }
    __syncthreads();

    // ---- ARel = rbin . rel_v   (all 256 threads: 4 t-chunks x 64 dims) ----
    {
        int dd = tid & 63, part = tid >> 6;
        int t0 = part * 32;
        int tn = (part == 3) ? 33 : 32;
        float acc = 0.f;
        for (int t = t0; t < t0 + tn; t++)
            acc += rbin[t] * __ldg(&relv[t * DHd + dd]);
        sred[part][dd] = acc;
    }
    __syncthreads();
    if (tid < DHd) {
        float a = (sred[0][tid] + sred[1][tid]) + (sred[2][tid] + sred[3][tid]);
        g_ARel[(size_t)row * DHd + tid] = a;
    }

    // ---- deterministic compaction (source order) ----
    int kc = 0;
    #pragma unroll
    for (int r = 0; r < 4; r++) if (sbuf[tid * 4 + r] >= 0.f) kc++;
    int p = kc;
    #pragma unroll
    for (int off = 1; off < 32; off <<= 1) {
        int v = __shfl_up_sync(0xffffffffu, p, off);
        if (lane >= off) p += v;
    }
    if (lane == 31) wredi[wid] = p;
    __syncthreads();
    int base = 0;
    #pragma unroll
    for (int w = 0; w < 8; w++) if (w < wid) base += wredi[w];
    int pos = base + p - kc;
    size_t cbase = (size_t)row * TOPKv;
    #pragma unroll
    for (int r = 0; r < 4; r++) {
        int j = tid * 4 + r;
        float e = sbuf[j];
        if (e >= 0.f) {
            if (pos < TOPKv) { g_CI[cbase + pos] = j; g_CW[cbase + pos] = e * inv; }
            pos++;
        }
    }
}

// =====================================================================
// Kernel 5: sparse apply v_out = attn @ v_in (+ARel on ord 0),
// Res (+)= sigmoid(alpha)*v_out. 512 threads, V half staged in smem.
// (proven R6 form)
// =====================================================================
__global__ __launch_bounds__(512) void k_apply(int ord, const float* __restrict__ alphas_raw) {
    extern __shared__ float smem[];
    float*  sV  = smem;                         // 1024*32 floats = 128 KB
    float2* sIW = (float2*)(smem + 1024 * 32);  // 16 warps * 256 = 32 KB

    const float* Vin  = (ord == 0) ? g_V  : ((ord == 1) ? g_VA : g_VB);
    float*       Vout = (ord == 0) ? g_VA : ((ord == 1) ? g_VB : g_VA);

    int bh = blockIdx.x >> 1;
    int d0 = (blockIdx.x & 1) * 32;
    int tid = threadIdx.x, wid = tid >> 5, lane = tid & 31;
    size_t vbase = (size_t)bh * NN * DHd;

    for (int e = tid; e < 1024 * 32; e += 512) {
        int r = e >> 5, c = e & 31;
        sV[e] = Vin[vbase + (size_t)r * DHd + d0 + c];
    }
    __syncthreads();

    int h = bh & (HH - 1);
    float araw = alphas_raw[ord * HH + h];
    float alpha = 1.0f / (1.0f + __expf(-araw));
    float2* myIW = sIW + wid * 256;

    for (int i = wid; i < NN; i += 16) {
        int row = bh * NN + i;
        const int*   ci = &g_CI[(size_t)row * TOPKv];
        const float* cw = &g_CW[(size_t)row * TOPKv];
        #pragma unroll
        for (int q = 0; q < 8; q++) {
            int p = q * 32 + lane;
            myIW[p] = make_float2(cw[p], __int_as_float(ci[p]));
        }
        __syncwarp();
        float a0 = 0.f, a1 = 0.f, a2 = 0.f, a3 = 0.f;
        #pragma unroll 4
        for (int p = 0; p < TOPKv; p += 4) {
            float2 w0 = myIW[p+0], w1 = myIW[p+1], w2 = myIW[p+2], w3 = myIW[p+3];
            a0 += w0.x * sV[__float_as_int(w0.y) * 32 + lane];
            a1 += w1.x * sV[__float_as_int(w1.y) * 32 + lane];
            a2 += w2.x * sV[__float_as_int(w2.y) * 32 + lane];
            a3 += w3.x * sV[__float_as_int(w3.y) * 32 + lane];
        }
        float acc = (a0 + a1) + (a2 + a3);
        __syncwarp();
        size_t oidx = (size_t)row * DHd + d0 + lane;
        if (ord == 0) acc += g_ARel[oidx];
        Vout[oidx] = acc;
        float rv = alpha * acc;
        if (ord == 0) g_Res[oidx] = rv;
        else          g_Res[oidx] += rv;
    }
}

// =====================================================================
// Kernel 6: out = res_flat @ Wout^T + bout.  128x128 tile, BK=16,
// reg double-buffered, FFMA2.
// =====================================================================
__global__ __launch_bounds__(256) void k_gemm_out(const float* __restrict__ W,
                                                  const float* __restrict__ bias,
                                                  float* __restrict__ out) {
    __shared__ float As[16][128];
    __shared__ float Bs[16][128];
    int tid = threadIdx.x;
    int tx = tid & 15, ty = tid >> 4;
    int m0 = blockIdx.y * 128, o0 = blockIdx.x * 128;
    u64 acc2[8][4] = {};

    int lr0 = tid >> 2, lk = (tid & 3) * 4;
    int lr1 = lr0 + 64;
    int m_0 = m0 + lr0, m_1 = m0 + lr1;
    int b_0 = m_0 >> 10, n_0 = m_0 & 1023;
    int b_1 = m_1 >> 10, n_1 = m_1 & 1023;
    const float* pb0 = &W[(size_t)(o0 + lr0) * DIMV + lk];
    const float* pb1 = &W[(size_t)(o0 + lr1) * DIMV + lk];

    auto aptr = [&](int b, int n, int k) {
        return &g_Res[((size_t)((b * HH + (k >> 6)) * NN + n)) * DHd + (k & 63)];
    };

    float4 ra0 = *(const float4*)aptr(b_0, n_0, lk);
    float4 ra1 = *(const float4*)aptr(b_1, n_1, lk);
    float4 rb0 = *(const float4*)pb0;
    float4 rb1 = *(const float4*)pb1;

    for (int k0 = 0; k0 < DIMV; k0 += 16) {
        As[lk+0][lr0] = ra0.x; As[lk+1][lr0] = ra0.y; As[lk+2][lr0] = ra0.z; As[lk+3][lr0] = ra0.w;
        As[lk+0][lr1] = ra1.x; As[lk+1][lr1] = ra1.y; As[lk+2][lr1] = ra1.z; As[lk+3][lr1] = ra1.w;
        Bs[lk+0][lr0] = rb0.x; Bs[lk+1][lr0] = rb0.y; Bs[lk+2][lr0] = rb0.z; Bs[lk+3][lr0] = rb0.w;
        Bs[lk+0][lr1] = rb1.x; Bs[lk+1][lr1] = rb1.y; Bs[lk+2][lr1] = rb1.z; Bs[lk+3][lr1] = rb1.w;
        __syncthreads();
        if (k0 + 16 < DIMV) {
            ra0 = *(const float4*)aptr(b_0, n_0, k0 + 16 + lk);
            ra1 = *(const float4*)aptr(b_1, n_1, k0 + 16 + lk);
            rb0 = *(const float4*)(pb0 + k0 + 16);
            rb1 = *(const float4*)(pb1 + k0 + 16);
        }
        #pragma unroll
        for (int k = 0; k < 16; k++) {
            float4 a0 = *(const float4*)&As[k][ty * 4];
            float4 a1 = *(const float4*)&As[k][ty * 4 + 64];
            ulonglong2 b0 = *(const ulonglong2*)&Bs[k][tx * 4];
            ulonglong2 b1 = *(const ulonglong2*)&Bs[k][tx * 4 + 64];
            u64 ad[8];
            ad[0]=dup2(a0.x); ad[1]=dup2(a0.y); ad[2]=dup2(a0.z); ad[3]=dup2(a0.w);
            ad[4]=dup2(a1.x); ad[5]=dup2(a1.y); ad[6]=dup2(a1.z); ad[7]=dup2(a1.w);
            #pragma unroll
            for (int i = 0; i < 8; i++) {
                ffma2(acc2[i][0], ad[i], b0.x);
                ffma2(acc2[i][1], ad[i], b0.y);
                ffma2(acc2[i][2], ad[i], b1.x);
                ffma2(acc2[i][3], ad[i], b1.y);
            }
        }
        __syncthreads();
    }
    #pragma unroll
    for (int ih = 0; ih < 2; ih++) {
        #pragma unroll
        for (int i = 0; i < 4; i++) {
            int m = m0 + ih * 64 + ty * 4 + i;
            #pragma unroll
            for (int jh = 0; jh < 2; jh++) {
                int o = o0 + jh * 64 + tx * 4;
                float2 lo = unpack2(acc2[ih*4+i][jh*2+0]);
                float2 hi = unpack2(acc2[ih*4+i][jh*2+1]);
                float4 v;
                v.x = lo.x + bias[o+0];
                v.y = lo.y + bias[o+1];
                v.z = hi.x + bias[o+2];
                v.w = hi.y + bias[o+3];
                *(float4*)&out[(size_t)m * DIMV + o] = v;
            }
        }
    }
}

// =====================================================================
extern "C" void kernel_launch(void* const* d_in, const int* in_sizes, int n_in,
                              void* d_out, int out_size) {
    const float* x      = (const float*)d_in[0];
    const float* Wqkv   = (const float*)d_in[1];
    const float* bqkv   = (const float*)d_in[2];
    const float* Wout   = (const float*)d_in[3];
    const float* bout   = (const float*)d_in[4];
    const float* relk   = (const float*)d_in[5];
    const float* relv   = (const float*)d_in[6];
    const float* alphas = (const float*)d_in[7];
    float* out = (float*)d_out;

    k_gemm_qkv<<<dim3(24, 32), 256>>>(x, Wqkv, bqkv);
    k_qr<<<ROWS / 32, 256>>>(relk);
    k_scores<<<dim3(8, 8, BHH), 256>>>();
    k_select<<<ROWS, 256>>>(relv);

    cudaFuncSetAttribute(k_apply, cudaFuncAttributeMaxDynamicSharedMemorySize, 163840);
    k_apply<<<BHH * 2, 512, 163840>>>(0, alphas);
    k_apply<<<BHH * 2, 512, 163840>>>(1, alphas);
    k_apply<<<BHH * 2, 512, 163840>>>(2, alphas);

    k_gemm_out<<<dim3(8, 32), 256>>>(Wout, bout, out);
}

// round 10
// speedup vs baseline: 2.0435x; 2.0435x over previous
#include <cuda_runtime.h>
#include <cuda_fp16.h>

// ---------------- problem constants ----------------
#define Bb 4
#define NN 1024
#define DIMV 1024
#define HH 16
#define DHd 64
#define VOC 129            // 2*MAXREL+1
#define MAXREL 64
#define TOPKv 256
#define BHH (Bb*HH)        // 64
#define ROWS (BHH*NN)      // 65536
#define SCALEv 0.125f      // DH^-0.5

typedef unsigned long long u64;

// ---------------- device scratch (no allocs allowed) ----------------
__device__ float g_Q[ROWS*DHd];
__device__ float g_K[ROWS*DHd];
__device__ __half g_V16[ROWS*DHd];
__device__ float g_S[(size_t)ROWS*NN];        // 256 MB scores
__device__ float g_QR[ROWS*VOC];              // q @ rel_k_emb^T
__device__ float g_CW[ROWS*TOPKv];            // compact attn weights
__device__ int   g_CI[ROWS*TOPKv];            // compact attn column indices
__device__ float g_ARel[ROWS*DHd];            // attn @ rel_v
__device__ __half g_VA16[ROWS*DHd];
__device__ __half g_VB16[ROWS*DHd];
__device__ float g_Res[ROWS*DHd];

// ---------------- packed f32x2 helpers ----------------
__device__ __forceinline__ void ffma2(u64 &d, u64 a, u64 b) {
    asm("fma.rn.f32x2 %0, %1, %2, %0;" : "+l"(d) : "l"(a), "l"(b));
}
__device__ __forceinline__ u64 dup2(float x) {
    u64 r; asm("mov.b64 %0, {%1, %1};" : "=l"(r) : "f"(x)); return r;
}
__device__ __forceinline__ float2 unpack2(u64 v) {
    float2 f; asm("mov.b64 {%0, %1}, %2;" : "=f"(f.x), "=f"(f.y) : "l"(v)); return f;
}

// =====================================================================
// Kernel 1: qkv = x @ Wqkv^T + bqkv, scattered into per-head Q/K (fp32)
// and V (fp16). 128x128 tile, BK=16, reg double-buffered, FFMA2.
// =====================================================================
__global__ __launch_bounds__(256) void k_gemm_qkv(const float* __restrict__ X,
                                                  const float* __restrict__ W,
                                                  const float* __restrict__ bias) {
    __shared__ float As[16][128];
    __shared__ float Bs[16][128];
    int tid = threadIdx.x;
    int tx = tid & 15, ty = tid >> 4;
    int m0 = blockIdx.y * 128, c0 = blockIdx.x * 128;
    u64 acc2[8][4] = {};

    int lr0 = tid >> 2, lk = (tid & 3) * 4;
    int lr1 = lr0 + 64;
    const float* pa0 = &X[(size_t)(m0 + lr0) * DIMV + lk];
    const float* pa1 = &X[(size_t)(m0 + lr1) * DIMV + lk];
    const float* pb0 = &W[(size_t)(c0 + lr0) * DIMV + lk];
    const float* pb1 = &W[(size_t)(c0 + lr1) * DIMV + lk];

    float4 ra0 = *(const float4*)pa0;
    float4 ra1 = *(const float4*)pa1;
    float4 rb0 = *(const float4*)pb0;
    float4 rb1 = *(const float4*)pb1;

    for (int k0 = 0; k0 < DIMV; k0 += 16) {
        As[lk+0][lr0] = ra0.x; As[lk+1][lr0] = ra0.y; As[lk+2][lr0] = ra0.z; As[lk+3][lr0] = ra0.w;
        As[lk+0][lr1] = ra1.x; As[lk+1][lr1] = ra1.y; As[lk+2][lr1] = ra1.z; As[lk+3][lr1] = ra1.w;
        Bs[lk+0][lr0] = rb0.x; Bs[lk+1][lr0] = rb0.y; Bs[lk+2][lr0] = rb0.z; Bs[lk+3][lr0] = rb0.w;
        Bs[lk+0][lr1] = rb1.x; Bs[lk+1][lr1] = rb1.y; Bs[lk+2][lr1] = rb1.z; Bs[lk+3][lr1] = rb1.w;
        __syncthreads();
        if (k0 + 16 < DIMV) {
            ra0 = *(const float4*)(pa0 + k0 + 16);
            ra1 = *(const float4*)(pa1 + k0 + 16);
            rb0 = *(const float4*)(pb0 + k0 + 16);
            rb1 = *(const float4*)(pb1 + k0 + 16);
        }
        #pragma unroll
        for (int k = 0; k < 16; k++) {
            float4 a0 = *(const float4*)&As[k][ty * 4];
            float4 a1 = *(const float4*)&As[k][ty * 4 + 64];
            ulonglong2 b0 = *(const ulonglong2*)&Bs[k][tx * 4];
            ulonglong2 b1 = *(const ulonglong2*)&Bs[k][tx * 4 + 64];
            u64 ad[8];
            ad[0]=dup2(a0.x); ad[1]=dup2(a0.y); ad[2]=dup2(a0.z); ad[3]=dup2(a0.w);
            ad[4]=dup2(a1.x); ad[5]=dup2(a1.y); ad[6]=dup2(a1.z); ad[7]=dup2(a1.w);
            #pragma unroll
            for (int i = 0; i < 8; i++) {
                ffma2(acc2[i][0], ad[i], b0.x);
                ffma2(acc2[i][1], ad[i], b0.y);
                ffma2(acc2[i][2], ad[i], b1.x);
                ffma2(acc2[i][3], ad[i], b1.y);
            }
        }
        __syncthreads();
    }
    #pragma unroll
    for (int ih = 0; ih < 2; ih++) {
        #pragma unroll
        for (int i = 0; i < 4; i++) {
            int m = m0 + ih * 64 + ty * 4 + i;
            int b = m >> 10, n = m & 1023;
            #pragma unroll
            for (int jh = 0; jh < 2; jh++) {
                int c = c0 + jh * 64 + tx * 4;
                float2 lo = unpack2(acc2[ih*4+i][jh*2+0]);
                float2 hi = unpack2(acc2[ih*4+i][jh*2+1]);
                float4 v;
                v.x = lo.x + bias[c+0];
                v.y = lo.y + bias[c+1];
                v.z = hi.x + bias[c+2];
                v.w = hi.y + bias[c+3];
                int part = c >> 10;
                int hc = c & 1023;
                int h = hc >> 6, dh = hc & 63;
                size_t idx = ((size_t)((b * HH + h) * NN + n)) * DHd + dh;
                if (part < 2) {
                    float* dst = (part == 0) ? g_Q : g_K;
                    *(float4*)&dst[idx] = v;
                } else {
                    __half2 h01 = __floats2half2_rn(v.x, v.y);
                    __half2 h23 = __floats2half2_rn(v.z, v.w);
                    uint2 pk;
                    pk.x = *(unsigned*)&h01;
                    pk.y = *(unsigned*)&h23;
                    *(uint2*)&g_V16[idx] = pk;
                }
            }
        }
    }
}

// =====================================================================
// Kernel 2: QR[row][t] = Q[row] . rel_k_emb[t]
// rel_k staged in smem transposed [d][t], LDS.128 + FFMA2 inner.
// =====================================================================
__global__ __launch_bounds__(256) void k_qr(const float* __restrict__ relk) {
    __shared__ float sQ[32][68];
    __shared__ float srk[64][132];   // [d][t], t padded to 132 (zero pad)
    int tid = threadIdx.x;
    int row0 = blockIdx.x * 32;
    for (int e = tid; e < 32 * 64; e += 256) {
        int r = e >> 6, d = e & 63;
        sQ[r][d] = g_Q[(size_t)(row0 + r) * DHd + d];
    }
    for (int e = tid; e < 64 * 132; e += 256) {
        int d = e / 132, t = e % 132;
        srk[d][t] = (t < VOC) ? relk[t * DHd + d] : 0.f;
    }
    __syncthreads();
    // 32 rows x 33 t-quads
    for (int g = tid; g < 32 * 33; g += 256) {
        int r = g / 33, tt = g % 33;
        u64 a01 = 0, a23 = 0;
        #pragma unroll 16
        for (int d = 0; d < 64; d++) {
            u64 qd = dup2(sQ[r][d]);
            ulonglong2 f = *(const ulonglong2*)&srk[d][tt * 4];
            ffma2(a01, qd, f.x);
            ffma2(a23, qd, f.y);
        }
        float2 lo = unpack2(a01), hi = unpack2(a23);
        size_t base = (size_t)(row0 + r) * VOC;
        int t0 = tt * 4;
        if (tt < 32) {
            g_QR[base + t0 + 0] = lo.x;
            g_QR[base + t0 + 1] = lo.y;
            g_QR[base + t0 + 2] = hi.x;
            g_QR[base + t0 + 3] = hi.y;
        } else {
            g_QR[base + 128] = lo.x;
        }
    }
}

// =====================================================================
// Kernel 3: S = SCALE*Q.K^T + QR gather.  128x128 tile, BK=16, FFMA2.
// grid (8, 8, 64)   (proven form)
// =====================================================================
__global__ __launch_bounds__(256) void k_scores() {
    __shared__ float Qs[16][128];
    __shared__ float Ks[16][128];
    int tid = threadIdx.x;
    int tx = tid & 15, ty = tid >> 4;
    int bh = blockIdx.z;
    int i0 = blockIdx.y * 128, j0 = blockIdx.x * 128;
    size_t qbase = (size_t)(bh * NN + i0) * DHd;
    size_t kbase = (size_t)(bh * NN + j0) * DHd;
    u64 acc2[8][4] = {};

    for (int k0 = 0; k0 < DHd; k0 += 16) {
        #pragma unroll
        for (int it = 0; it < 2; it++) {
            int f = tid + it * 256;
            int r = f >> 2, kc = (f & 3) * 4;
            float4 qv = *(const float4*)&g_Q[qbase + (size_t)r * DHd + k0 + kc];
            float4 kv = *(const float4*)&g_K[kbase + (size_t)r * DHd + k0 + kc];
            Qs[kc+0][r] = qv.x; Qs[kc+1][r] = qv.y; Qs[kc+2][r] = qv.z; Qs[kc+3][r] = qv.w;
            Ks[kc+0][r] = kv.x; Ks[kc+1][r] = kv.y; Ks[kc+2][r] = kv.z; Ks[kc+3][r] = kv.w;
        }
        __syncthreads();
        #pragma unroll
        for (int k = 0; k < 16; k++) {
            float4 a0 = *(const float4*)&Qs[k][ty * 4];
            float4 a1 = *(const float4*)&Qs[k][ty * 4 + 64];
            ulonglong2 b0 = *(const ulonglong2*)&Ks[k][tx * 4];
            ulonglong2 b1 = *(const ulonglong2*)&Ks[k][tx * 4 + 64];
            u64 ad[8];
            ad[0]=dup2(a0.x); ad[1]=dup2(a0.y); ad[2]=dup2(a0.z); ad[3]=dup2(a0.w);
            ad[4]=dup2(a1.x); ad[5]=dup2(a1.y); ad[6]=dup2(a1.z); ad[7]=dup2(a1.w);
            #pragma unroll
            for (int i = 0; i < 8; i++) {
                ffma2(acc2[i][0], ad[i], b0.x);
                ffma2(acc2[i][1], ad[i], b0.y);
                ffma2(acc2[i][2], ad[i], b1.x);
                ffma2(acc2[i][3], ad[i], b1.y);
            }
        }
        __syncthreads();
    }
    #pragma unroll
    for (int ih = 0; ih < 2; ih++) {
        #pragma unroll
        for (int i = 0; i < 4; i++) {
            int ii = i0 + ih * 64 + ty * 4 + i;
            const float* qr = &g_QR[(size_t)(bh * NN + ii) * VOC];
            size_t sbase = ((size_t)(bh * NN + ii)) * NN;
            #pragma unroll
            for (int jh = 0; jh < 2; jh++) {
                int jj0 = j0 + jh * 64 + tx * 4;
                float2 lo = unpack2(acc2[ih*4+i][jh*2+0]);
                float2 hi = unpack2(acc2[ih*4+i][jh*2+1]);
                float accv[4] = {lo.x, lo.y, hi.x, hi.y};
                float4 v;
                #pragma unroll
                for (int j = 0; j < 4; j++) {
                    int jj = jj0 + j;
                    int d = ii - jj;
                    d = d < -MAXREL ? -MAXREL : (d > MAXREL ? MAXREL : d);
                    ((float*)&v)[j] = accv[j] * SCALEv + qr[d + MAXREL];
                }
                *(float4*)&g_S[sbase + jj0] = v;
            }
        }
    }
}

// float -> order-preserving uint key
__device__ __forceinline__ unsigned ftokey(float f) {
    unsigned u = __float_as_uint(f);
    return (u & 0x80000000u) ? ~u : (u | 0x80000000u);
}

// =====================================================================
// Kernel 4 (fused): radix-select exact top-256 threshold + masked softmax
// + deterministic compaction + rel_v bucket trick -> ARel.
// (proven R6 form) One block (256 threads) per score row.
// =====================================================================
__global__ __launch_bounds__(256) void k_select(const float* __restrict__ relv) {
    __shared__ float sbuf[1024];
    __shared__ int   hist[256];
    __shared__ float wredf[8];
    __shared__ float wredf2[8];
    __shared__ int   wredi[8];
    __shared__ float rbin[VOC];
    __shared__ unsigned sh_selb;
    __shared__ int      sh_rem;

    int row = blockIdx.x;
    int tid = threadIdx.x;
    int lane = tid & 31, wid = tid >> 5;
    int i = row & (NN - 1);
    const float* src = &g_S[(size_t)row * NN];

    float lv[4]; unsigned kv[4];
    #pragma unroll
    for (int r = 0; r < 4; r++) {
        int j = tid * 4 + r;
        lv[r] = src[j];
        kv[r] = ftokey(lv[r]);
    }

    // ---- row max ----
    float m = fmaxf(fmaxf(lv[0], lv[1]), fmaxf(lv[2], lv[3]));
    #pragma unroll
    for (int off = 16; off > 0; off >>= 1)
        m = fmaxf(m, __shfl_xor_sync(0xffffffffu, m, off));
    if (lane == 0) wredf[wid] = m;
    __syncthreads();
    float rmax = wredf[0];
    #pragma unroll
    for (int w = 1; w < 8; w++) rmax = fmaxf(rmax, wredf[w]);

    // ---- radix select: exact key of the 256th largest ----
    unsigned prefix = 0;
    int need = TOPKv;
    for (int round = 3; round >= 0; round--) {
        hist[tid] = 0;
        __syncthreads();
        unsigned mask = (round == 3) ? 0u : (0xFFFFFFFFu << ((round + 1) * 8));
        #pragma unroll
        for (int r = 0; r < 4; r++) {
            if ((kv[r] & mask) == prefix)
                atomicAdd(&hist[(kv[r] >> (round * 8)) & 255], 1);
        }
        __syncthreads();
        int h = hist[tid];
        int s = h;          // inclusive suffix within warp
        #pragma unroll
        for (int off = 1; off < 32; off <<= 1) {
            int v = __shfl_down_sync(0xffffffffu, s, off);
            if (lane + off < 32) s += v;
        }
        int wtot = __shfl_sync(0xffffffffu, s, 0);
        if (lane == 0) wredi[wid] = wtot;
        __syncthreads();
        int tail = 0;
        #pragma unroll
        for (int w = 0; w < 8; w++) if (w > wid) tail += wredi[w];
        int Sb = s + tail;          // count of keys >= bin tid
        int Sb1 = Sb - h;           // count of keys >= bin tid+1
        if (Sb >= need && Sb1 < need) { sh_selb = (unsigned)tid; sh_rem = Sb1; }
        __syncthreads();
        prefix |= sh_selb << (round * 8);
        need -= sh_rem;
        __syncthreads();
    }
    unsigned thrkey = prefix;

    // ---- masked exp + block sum ----
    float lsum = 0.f;
    #pragma unroll
    for (int r = 0; r < 4; r++) {
        int j = tid * 4 + r;
        float e;
        if (kv[r] >= thrkey) { e = __expf(lv[r] - rmax); lsum += e; }
        else e = -1.0f;
        sbuf[j] = e;
    }
    float ws = lsum;
    #pragma unroll
    for (int off = 16; off > 0; off >>= 1)
        ws += __shfl_xor_sync(0xffffffffu, ws, off);
    if (lane == 0) wredf[wid] = ws;
    __syncthreads();
    float tot = 0.f;
    #pragma unroll
    for (int w = 0; w < 8; w++) tot += wredf[w];
    float inv = 1.0f / tot;

    // ---- rel_v buckets ----
    if (tid >= 1 && tid < 128) {
        int j = i + MAXREL - tid;
        float v = 0.f;
        if (j >= 0 && j < NN) {
            float e = sbuf[j];
            if (e >= 0.f) v = e * inv;
        }
        rbin[tid] = v;
    }
    float s0 = 0.f, s128 = 0.f;
    #pragma unroll
    for (int r = 0; r < 4; r++) {
        int j = tid * 4 + r;
        float e = sbuf[j];
        float a = (e >= 0.f) ? e * inv : 0.f;
        if (j >= i + MAXREL) s0 += a;
        if (j <= i - MAXREL) s128 += a;
    }
    #pragma unroll
    for (int off = 16; off > 0; off >>= 1) {
        s0   += __shfl_xor_sync(0xffffffffu, s0, off);
        s128 += __shfl_xor_sync(0xffffffffu, s128, off);
    }
    __syncthreads();
    if (lane == 0) { wredf[wid] = s0; wredf2[wid] = s128; }
    __syncthreads();
    if (tid == 0) {
        float a = 0.f, b = 0.f;
        #pragma unroll
        for (int w = 0; w < 8; w++) { a += wredf[w]; b += wredf2[w]; }
        rbin[0] = a; rbin[MAXREL * 2] = b;
    }
    __syncthreads();

    if (tid < DHd) {
        float acc = 0.f;
        #pragma unroll
        for (int t = 0; t < VOC; t++) acc += rbin[t] * __ldg(&relv[t * DHd + tid]);
        g_ARel[(size_t)row * DHd + tid] = acc;
    }

    // ---- deterministic compaction (source order) ----
    int kc = 0;
    #pragma unroll
    for (int r = 0; r < 4; r++) if (sbuf[tid * 4 + r] >= 0.f) kc++;
    int p = kc;
    #pragma unroll
    for (int off = 1; off < 32; off <<= 1) {
        int v = __shfl_up_sync(0xffffffffu, p, off);
        if (lane >= off) p += v;
    }
    if (lane == 31) wredi[wid] = p;
    __syncthreads();
    int base = 0;
    #pragma unroll
    for (int w = 0; w < 8; w++) if (w < wid) base += wredi[w];
    int pos = base + p - kc;
    size_t cbase = (size_t)row * TOPKv;
    #pragma unroll
    for (int r = 0; r < 4; r++) {
        int j = tid * 4 + r;
        float e = sbuf[j];
        if (e >= 0.f) {
            if (pos < TOPKv) { g_CI[cbase + pos] = j; g_CW[cbase + pos] = e * inv; }
            pos++;
        }
    }
}

// =====================================================================
// Kernel 5: sparse apply with fp16 V packed as half2 per d-pair.
// One block covers ALL 64 d for a row-half of one bh => crossbar
// wavefronts halved vs fp32 two-d-half layout.
// grid (bh, row-half) = 128 blocks, 512 threads.
// =====================================================================
__global__ __launch_bounds__(512) void k_apply(int ord, const float* __restrict__ alphas_raw) {
    extern __shared__ char smemc[];
    unsigned* sVu = (unsigned*)smemc;                  // 1024 rows x 32 uints = 128 KB
    float2*   sIW = (float2*)(smemc + 1024 * 32 * 4);  // 16 warps * 256 * 8B = 32 KB

    const __half* Vin16  = (ord == 0) ? g_V16  : ((ord == 1) ? g_VA16 : g_VB16);
    __half*       Vout16 = (ord == 0) ? g_VA16 : ((ord == 1) ? g_VB16 : g_VA16);

    int bh = blockIdx.x >> 1;
    int rh = blockIdx.x & 1;
    int tid = threadIdx.x, wid = tid >> 5, lane = tid & 31;

    // stage V for this bh (full 1024 x 64 fp16 = 128 KB), coalesced uint4
    {
        const uint4* srcv = (const uint4*)(Vin16 + (size_t)bh * NN * DHd);
        uint4* dstv = (uint4*)sVu;
        for (int e = tid; e < 8192; e += 512) dstv[e] = srcv[e];
    }
    __syncthreads();

    int h = bh & (HH - 1);
    float araw = alphas_raw[ord * HH + h];
    float alpha = 1.0f / (1.0f + __expf(-araw));
    float2* myIW = sIW + wid * 256;

    for (int i = rh * 512 + wid; i < rh * 512 + 512; i += 16) {
        int row = bh * NN + i;
        const int*   ci = &g_CI[(size_t)row * TOPKv];
        const float* cw = &g_CW[(size_t)row * TOPKv];
        #pragma unroll
        for (int q = 0; q < 8; q++) {
            int p = q * 32 + lane;
            myIW[p] = make_float2(cw[p], __int_as_float(ci[p]));
        }
        __syncwarp();
        float2 a0 = {0.f, 0.f}, a1 = {0.f, 0.f}, a2 = {0.f, 0.f}, a3 = {0.f, 0.f};
        #pragma unroll 4
        for (int p = 0; p < TOPKv; p += 4) {
            float2 w0 = myIW[p+0], w1 = myIW[p+1], w2 = myIW[p+2], w3 = myIW[p+3];
            unsigned u0 = sVu[__float_as_int(w0.y) * 32 + lane];
            unsigned u1 = sVu[__float_as_int(w1.y) * 32 + lane];
            unsigned u2 = sVu[__float_as_int(w2.y) * 32 + lane];
            unsigned u3 = sVu[__float_as_int(w3.y) * 32 + lane];
            float2 v0 = __half22float2(*(__half2*)&u0);
            float2 v1 = __half22float2(*(__half2*)&u1);
            float2 v2 = __half22float2(*(__half2*)&u2);
            float2 v3 = __half22float2(*(__half2*)&u3);
            a0.x += w0.x * v0.x; a0.y += w0.x * v0.y;
            a1.x += w1.x * v1.x; a1.y += w1.x * v1.y;
            a2.x += w2.x * v2.x; a2.y += w2.x * v2.y;
            a3.x += w3.x * v3.x; a3.y += w3.x * v3.y;
        }
        float2 acc;
        acc.x = (a0.x + a1.x) + (a2.x + a3.x);
        acc.y = (a0.y + a1.y) + (a2.y + a3.y);
        __syncwarp();

        size_t oidx = (size_t)row * DHd + 2 * lane;
        if (ord == 0) {
            float2 ar = *(const float2*)&g_ARel[oidx];
            acc.x += ar.x; acc.y += ar.y;
        }
        // write next-order V in fp16
        __half2 hv = __floats2half2_rn(acc.x, acc.y);
        *(unsigned*)&Vout16[oidx] = *(unsigned*)&hv;
        // accumulate result in fp32
        if (ord == 0) {
            float2 rv = make_float2(alpha * acc.x, alpha * acc.y);
            *(float2*)&g_Res[oidx] = rv;
        } else {
            float2 pr = *(float2*)&g_Res[oidx];
            pr.x += alpha * acc.x;
            pr.y += alpha * acc.y;
            *(float2*)&g_Res[oidx] = pr;
        }
    }
}

// =====================================================================
// Kernel 6: out = res_flat @ Wout^T + bout.  128x128 tile, BK=16,
// reg double-buffered, FFMA2.
// =====================================================================
__global__ __launch_bounds__(256) void k_gemm_out(const float* __restrict__ W,
                                                  const float* __restrict__ bias,
                                                  float* __restrict__ out) {
    __shared__ float As[16][128];
    __shared__ float Bs[16][128];
    int tid = threadIdx.x;
    int tx = tid & 15, ty = tid >> 4;
    int m0 = blockIdx.y * 128, o0 = blockIdx.x * 128;
    u64 acc2[8][4] = {};

    int lr0 = tid >> 2, lk = (tid & 3) * 4;
    int lr1 = lr0 + 64;
    int m_0 = m0 + lr0, m_1 = m0 + lr1;
    int b_0 = m_0 >> 10, n_0 = m_0 & 1023;
    int b_1 = m_1 >> 10, n_1 = m_1 & 1023;
    const float* pb0 = &W[(size_t)(o0 + lr0) * DIMV + lk];
    const float* pb1 = &W[(size_t)(o0 + lr1) * DIMV + lk];

    auto aptr = [&](int b, int n, int k) {
        return &g_Res[((size_t)((b * HH + (k >> 6)) * NN + n)) * DHd + (k & 63)];
    };

    float4 ra0 = *(const float4*)aptr(b_0, n_0, lk);
    float4 ra1 = *(const float4*)aptr(b_1, n_1, lk);
    float4 rb0 = *(const float4*)pb0;
    float4 rb1 = *(const float4*)pb1;

    for (int k0 = 0; k0 < DIMV; k0 += 16) {
        As[lk+0][lr0] = ra0.x; As[lk+1][lr0] = ra0.y; As[lk+2][lr0] = ra0.z; As[lk+3][lr0] = ra0.w;
        As[lk+0][lr1] = ra1.x; As[lk+1][lr1] = ra1.y; As[lk+2][lr1] = ra1.z; As[lk+3][lr1] = ra1.w;
        Bs[lk+0][lr0] = rb0.x; Bs[lk+1][lr0] = rb0.y; Bs[lk+2][lr0] = rb0.z; Bs[lk+3][lr0] = rb0.w;
        Bs[lk+0][lr1] = rb1.x; Bs[lk+1][lr1] = rb1.y; Bs[lk+2][lr1] = rb1.z; Bs[lk+3][lr1] = rb1.w;
        __syncthreads();
        if (k0 + 16 < DIMV) {
            ra0 = *(const float4*)aptr(b_0, n_0, k0 + 16 + lk);
            ra1 = *(const float4*)aptr(b_1, n_1, k0 + 16 + lk);
            rb0 = *(const float4*)(pb0 + k0 + 16);
            rb1 = *(const float4*)(pb1 + k0 + 16);
        }
        #pragma unroll
        for (int k = 0; k < 16; k++) {
            float4 a0 = *(const float4*)&As[k][ty * 4];
            float4 a1 = *(const float4*)&As[k][ty * 4 + 64];
            ulonglong2 b0 = *(const ulonglong2*)&Bs[k][tx * 4];
            ulonglong2 b1 = *(const ulonglong2*)&Bs[k][tx * 4 + 64];
            u64 ad[8];
            ad[0]=dup2(a0.x); ad[1]=dup2(a0.y); ad[2]=dup2(a0.z); ad[3]=dup2(a0.w);
            ad[4]=dup2(a1.x); ad[5]=dup2(a1.y); ad[6]=dup2(a1.z); ad[7]=dup2(a1.w);
            #pragma unroll
            for (int i = 0; i < 8; i++) {
                ffma2(acc2[i][0], ad[i], b0.x);
                ffma2(acc2[i][1], ad[i], b0.y);
                ffma2(acc2[i][2], ad[i], b1.x);
                ffma2(acc2[i][3], ad[i], b1.y);
            }
        }
        __syncthreads();
    }
    #pragma unroll
    for (int ih = 0; ih < 2; ih++) {
        #pragma unroll
        for (int i = 0; i < 4; i++) {
            int m = m0 + ih * 64 + ty * 4 + i;
            #pragma unroll
            for (int jh = 0; jh < 2; jh++) {
                int o = o0 + jh * 64 + tx * 4;
                float2 lo = unpack2(acc2[ih*4+i][jh*2+0]);
                float2 hi = unpack2(acc2[ih*4+i][jh*2+1]);
                float4 v;
                v.x = lo.x + bias[o+0];
                v.y = lo.y + bias[o+1];
                v.z = hi.x + bias[o+2];
                v.w = hi.y + bias[o+3];
                *(float4*)&out[(size_t)m * DIMV + o] = v;
            }
        }
    }
}

// =====================================================================
extern "C" void kernel_launch(void* const* d_in, const int* in_sizes, int n_in,
                              void* d_out, int out_size) {
    const float* x      = (const float*)d_in[0];
    const float* Wqkv   = (const float*)d_in[1];
    const float* bqkv   = (const float*)d_in[2];
    const float* Wout   = (const float*)d_in[3];
    const float* bout   = (const float*)d_in[4];
    const float* relk   = (const float*)d_in[5];
    const float* relv   = (const float*)d_in[6];
    const float* alphas = (const float*)d_in[7];
    float* out = (float*)d_out;

    k_gemm_qkv<<<dim3(24, 32), 256>>>(x, Wqkv, bqkv);
    k_qr<<<ROWS / 32, 256>>>(relk);
    k_scores<<<dim3(8, 8, BHH), 256>>>();
    k_select<<<ROWS, 256>>>(relv);

    cudaFuncSetAttribute(k_apply, cudaFuncAttributeMaxDynamicSharedMemorySize, 163840);
    k_apply<<<BHH * 2, 512, 163840>>>(0, alphas);
    k_apply<<<BHH * 2, 512, 163840>>>(1, alphas);
    k_apply<<<BHH * 2, 512, 163840>>>(2, alphas);

    k_gemm_out<<<dim3(8, 32), 256>>>(Wout, bout, out);
}